// round 8
// baseline (speedup 1.0000x reference)
#include <cuda_runtime.h>
#include <math_constants.h>

// KNN min-dist, 9x9 window, C=3, zero-padded.
// d^2 = |t|^2 + (|o|^2 - 2 t.o), q=|o|^2 in float4.w -> 3 FFMA + 1 FMNMX/shift.
// dj-SPLIT across warp halves: 256 threads per 32x16 tile; half A does dj 0..4,
// half B dj 5..8 for the SAME pixels; combine via smem. Doubles resident warps
// (28 -> ~55/SM) at identical LDS/FFMA totals, so crossbar and fma overlap.
// Fixed shapes: B=4, C=3, H=256, W=512.

#define BDIM 256
#define TW 32
#define TH 16
#define TY 4
#define HALO 4
#define SW 9

#define B_ 4
#define H_ 256
#define W_ 512
#define HW_ (H_*W_)

#define SH_H (TH + 2*HALO)   // 24
#define SH_W (TW + 2*HALO)   // 40
#define NR (TY + SW - 1)     // 12

__global__ __launch_bounds__(BDIM, 7) void knn_min_kernel(
    const float* __restrict__ tfm, const float* __restrict__ obs,
    float* __restrict__ out)
{
    __shared__ float4 s4[SH_H][SH_W];   // (o0, o1, o2, |o|^2)
    __shared__ float mred[TH][TW];      // half-A partial mins

    const int b  = blockIdx.z;
    const int x0 = blockIdx.x * TW;
    const int y0 = blockIdx.y * TH;
    const int tid = threadIdx.x;
    const int half = tid >> 7;          // 0: dj 0..4, 1: dj 5..8
    const int hid  = tid & 127;
    const int tx = hid & 31;
    const int ty = hid >> 5;

    const float* obs_b = obs + b * 3 * HW_;
    const float* tfm_b = tfm + b * 3 * HW_;

    // ---- load obs tile (zero-padded halo), q = |o|^2 on the fly ----
    for (int idx = tid; idx < SH_H * SH_W; idx += BDIM) {
        int iy = idx / SH_W;
        int ix = idx - iy * SH_W;
        int gy = y0 - HALO + iy;
        int gx = x0 - HALO + ix;
        float v0 = 0.f, v1 = 0.f, v2 = 0.f;
        if (gy >= 0 && gy < H_ && gx >= 0 && gx < W_) {
            int g = gy * W_ + gx;
            v0 = obs_b[g];
            v1 = obs_b[HW_ + g];
            v2 = obs_b[2 * HW_ + g];
        }
        float q = fmaf(v2, v2, fmaf(v1, v1, v0 * v0));
        s4[iy][ix] = make_float4(v0, v1, v2, q);
    }
    __syncthreads();

    // ---- per-pixel constants: nt_c = -2 t_c (tt only needed by half B) ----
    const int ybase = y0 + ty * TY;
    const int xg = x0 + tx;
    float nt0[TY], nt1[TY], nt2[TY], m[TY];
#pragma unroll
    for (int k = 0; k < TY; k++) {
        int g = (ybase + k) * W_ + xg;
        nt0[k] = -2.f * tfm_b[g];
        nt1[k] = -2.f * tfm_b[HW_ + g];
        nt2[k] = -2.f * tfm_b[2 * HW_ + g];
        m[k] = CUDART_INF_F;
    }

    const int rbase = ty * TY;

#define COL_PASS(DJ)                                                        \
    {                                                                       \
        _Pragma("unroll")                                                   \
        for (int r = 0; r < NR; r++) {                                      \
            const float4 v = s4[rbase + r][tx + (DJ)];                      \
            _Pragma("unroll")                                               \
            for (int k = 0; k < TY; k++) {                                  \
                if (r >= k && r <= k + 8) {                                 \
                    float e = fmaf(nt0[k], v.x,                             \
                              fmaf(nt1[k], v.y,                             \
                              fmaf(nt2[k], v.z, v.w)));                     \
                    m[k] = fminf(m[k], e);                                  \
                }                                                           \
            }                                                               \
        }                                                                   \
    }

    if (half == 0) {
#pragma unroll
        for (int dj = 0; dj < 5; dj++) COL_PASS(dj)
        // publish half-A partials
#pragma unroll
        for (int k = 0; k < TY; k++) mred[ty * TY + k][tx] = m[k];
    } else {
#pragma unroll
        for (int dj = 5; dj < 9; dj++) COL_PASS(dj)
    }
#undef COL_PASS

    __syncthreads();

    if (half == 1) {
        float* out_b = out + b * HW_;
#pragma unroll
        for (int k = 0; k < TY; k++) {
            int g = (ybase + k) * W_ + xg;
            // tt recomputed here (half B only) to keep register count low
            float a = tfm_b[g];
            float c = tfm_b[HW_ + g];
            float e = tfm_b[2 * HW_ + g];
            float tt = fmaf(e, e, fmaf(c, c, a * a));
            float mm = fminf(m[k], mred[ty * TY + k][tx]);
            out_b[g] = sqrtf(fmaxf(tt + mm, 0.f));
        }
    }
}

extern "C" void kernel_launch(void* const* d_in, const int* in_sizes, int n_in,
                              void* d_out, int out_size)
{
    const float* tfm = (const float*)d_in[0];
    const float* obs = (const float*)d_in[1];
    float* out = (float*)d_out;
    (void)in_sizes; (void)n_in; (void)out_size;

    dim3 grid(W_ / TW, H_ / TH, B_);   // 16 x 16 x 4 = 1024 blocks
    dim3 block(BDIM);
    knn_min_kernel<<<grid, block>>>(tfm, obs, out);
}

// round 9
// speedup vs baseline: 1.1248x; 1.1248x over previous
#include <cuda_runtime.h>
#include <math_constants.h>

// KNN min-dist, 9x9 window, C=3, zero-padded.
// d^2 = |t|^2 + (|o|^2 - 2 t.o); obs tile in 4 SoA smem planes (o0,o1,o2,q).
// Identical structure to R7 (flattened (dj,r) loop, 2-deep lookahead, dual min
// accumulators) but SCALAR LDS.32 loads instead of LDS.128: one wavefront per
// load, no within-instruction replay -> crossbar at full rate.
// Fixed shapes: B=4, C=3, H=256, W=512.

#define BDIM 128
#define TW 32
#define TH 16
#define TY 4
#define HALO 4
#define SW 9

#define B_ 4
#define H_ 256
#define W_ 512
#define HW_ (H_*W_)

#define SH_H (TH + 2*HALO)   // 24
#define SH_W (TW + 2*HALO)   // 40
#define PL   (SH_H * SH_W)   // 960 words per plane
#define NR (TY + SW - 1)     // 12
#define NITER (SW * NR)      // 108

__global__ __launch_bounds__(BDIM, 7) void knn_min_kernel(
    const float* __restrict__ tfm, const float* __restrict__ obs,
    float* __restrict__ out)
{
    __shared__ float sp[4][SH_H][SH_W];   // planes: o0, o1, o2, q=|o|^2

    const int b  = blockIdx.z;
    const int x0 = blockIdx.x * TW;
    const int y0 = blockIdx.y * TH;
    const int tid = threadIdx.x;
    const int tx = tid & 31;
    const int ty = tid >> 5;

    const float* obs_b = obs + b * 3 * HW_;
    const float* tfm_b = tfm + b * 3 * HW_;

    // ---- load obs tile (zero-padded halo), q = |o|^2 on the fly ----
    for (int idx = tid; idx < SH_H * SH_W; idx += BDIM) {
        int iy = idx / SH_W;
        int ix = idx - iy * SH_W;
        int gy = y0 - HALO + iy;
        int gx = x0 - HALO + ix;
        float v0 = 0.f, v1 = 0.f, v2 = 0.f;
        if (gy >= 0 && gy < H_ && gx >= 0 && gx < W_) {
            int g = gy * W_ + gx;
            v0 = obs_b[g];
            v1 = obs_b[HW_ + g];
            v2 = obs_b[2 * HW_ + g];
        }
        sp[0][iy][ix] = v0;
        sp[1][iy][ix] = v1;
        sp[2][iy][ix] = v2;
        sp[3][iy][ix] = fmaf(v2, v2, fmaf(v1, v1, v0 * v0));
    }
    __syncthreads();

    // ---- per-pixel constants: nt_c = -2 t_c, tt = |t|^2 ----
    const int ybase = y0 + ty * TY;
    const int xg = x0 + tx;
    float nt0[TY], nt1[TY], nt2[TY], tt[TY], m0[TY], m1[TY];
#pragma unroll
    for (int k = 0; k < TY; k++) {
        int g = (ybase + k) * W_ + xg;
        float a = tfm_b[g];
        float c = tfm_b[HW_ + g];
        float e = tfm_b[2 * HW_ + g];
        nt0[k] = -2.f * a;
        nt1[k] = -2.f * c;
        nt2[k] = -2.f * e;
        tt[k]  = fmaf(e, e, fmaf(c, c, a * a));
        m0[k] = CUDART_INF_F;
        m1[k] = CUDART_INF_F;
    }

    // Flat base at (row=ty*TY, col=tx) of plane 0; iteration i -> dj=i/NR,
    // r=i%NR; word offset = comp*PL + r*SH_W + dj (all immediate).
    const float* base = &sp[0][ty * TY][tx];
#define OFF(i, c) ((c) * PL + ((i) % NR) * SH_W + ((i) / NR))

    float b0[3], b1[3], b2[3], bq[3];
#pragma unroll
    for (int p = 0; p < 2; p++) {
        b0[p] = base[OFF(p, 0)];
        b1[p] = base[OFF(p, 1)];
        b2[p] = base[OFF(p, 2)];
        bq[p] = base[OFF(p, 3)];
    }

#pragma unroll
    for (int i = 0; i < NITER; i++) {
        if (i + 2 < NITER) {
            const int s = (i + 2) % 3;
            b0[s] = base[OFF(i + 2, 0)];
            b1[s] = base[OFF(i + 2, 1)];
            b2[s] = base[OFF(i + 2, 2)];
            bq[s] = base[OFF(i + 2, 3)];
        }
        const int c = i % 3;
        const float v0 = b0[c], v1 = b1[c], v2 = b2[c], vq = bq[c];
        const int dj = i / NR;
        const int r  = i % NR;
#pragma unroll
        for (int k = 0; k < TY; k++) {
            const int di = r - k;
            if (di >= 0 && di < SW) {
                float e = fmaf(nt0[k], v0,
                          fmaf(nt1[k], v1,
                          fmaf(nt2[k], v2, vq)));
                if (dj & 1) m1[k] = fminf(m1[k], e);
                else        m0[k] = fminf(m0[k], e);
            }
        }
    }
#undef OFF

    float* out_b = out + b * HW_;
#pragma unroll
    for (int k = 0; k < TY; k++) {
        float m = fminf(m0[k], m1[k]);
        out_b[(ybase + k) * W_ + xg] = sqrtf(fmaxf(tt[k] + m, 0.f));
    }
}

extern "C" void kernel_launch(void* const* d_in, const int* in_sizes, int n_in,
                              void* d_out, int out_size)
{
    const float* tfm = (const float*)d_in[0];
    const float* obs = (const float*)d_in[1];
    float* out = (float*)d_out;
    (void)in_sizes; (void)n_in; (void)out_size;

    dim3 grid(W_ / TW, H_ / TH, B_);   // 16 x 16 x 4 = 1024 blocks
    dim3 block(BDIM);
    knn_min_kernel<<<grid, block>>>(tfm, obs, out);
}